// round 1
// baseline (speedup 1.0000x reference)
#include <cuda_runtime.h>

// BatchSRU: L=2048, B=8, D=128, NB=16
//   U[l,b,nb,h] = sum_d x[l,b,d,nb] * W[nb,d,h]   (h in [0,384))
//   xt = U[:,:, :,0:128], f = sig(U[...,128:256]+bf), r = sig(U[...,256:384]+br)
//   c_t = f*c_{t-1} + (1-f)*xt ;  h = r*c + (1-r)*x ; out[l,b,d,nb] = h[l,b,nb,d]
//
// One persistent CTA per (b, nb): W[nb] resident in SMEM (196 KB), 128 threads,
// thread j owns channel d=j (state c in a register). Time blocked by 8 with
// packed f32x2 FMAs (time-pairs) and double-buffered x staging.

#define L_SEQ 2048
#define BATCH 8
#define DIM   128
#define NBI   16
#define TBLK  8
#define XSTRIDE (BATCH * DIM * NBI)   // 16384 floats per time step

typedef unsigned long long u64;

__device__ __forceinline__ u64 pack2(float lo, float hi) {
    u64 r;
    asm("mov.b64 %0, {%1, %2};" : "=l"(r) : "f"(lo), "f"(hi));
    return r;
}
__device__ __forceinline__ void unpack2(u64 v, float& lo, float& hi) {
    asm("mov.b64 {%0, %1}, %2;" : "=f"(lo), "=f"(hi) : "l"(v));
}
__device__ __forceinline__ void fma2(u64& d, u64 a, u64 b) {
    asm("fma.rn.f32x2 %0, %1, %2, %0;" : "+l"(d) : "l"(a), "l"(b));
}
__device__ __forceinline__ float sigmoidf_fast(float z) {
    return __fdividef(1.0f, 1.0f + __expf(-z));
}

// SMEM layout (floats): Wx [128k][128j] | Wf | Wr | xs [128k][8t]
#define SM_WX 0
#define SM_WF 16384
#define SM_WR 32768
#define SM_XS 49152
#define SMEM_BYTES ((49152 + 1024) * 4)   // 200704 B

__global__ void __launch_bounds__(128, 1) batch_sru_kernel(
    const float* __restrict__ x,
    const float* __restrict__ W,
    const float* __restrict__ bias,
    float* __restrict__ out)
{
    extern __shared__ float smem[];
    const int tid = threadIdx.x;          // = j (output channel) and = k (load lane)
    const int b   = blockIdx.x / NBI;
    const int nb  = blockIdx.x % NBI;

    // ---- Load W[nb] (128 x 384, row-major cols = [g*128 + j]) into SMEM as [g][k][j]
    {
        const float4* Wg4 = (const float4*)(W + (size_t)nb * (DIM * 3 * DIM));
        #pragma unroll 4
        for (int idx = tid; idx < (DIM * 3 * DIM) / 4; idx += 128) {
            float4 v = Wg4[idx];
            int e   = idx * 4;
            int k   = e / 384;
            int col = e - k * 384;
            int g   = col >> 7;
            int j   = col & 127;
            *(float4*)&smem[g * 16384 + k * 128 + j] = v;
        }
    }
    const float bfv = bias[nb * 256 + tid];
    const float brv = bias[nb * 256 + 128 + tid];

    const float* Wx = smem + SM_WX;
    const float* Wf = smem + SM_WF;
    const float* Wr = smem + SM_WR;
    float*       xs = smem + SM_XS;

    // x element for (t, b, k=tid, nb): x[t*XSTRIDE + xbase]
    const int xbase = (b * DIM + tid) * NBI + nb;
    float* outp = out + (b * DIM + tid) * NBI + nb;   // + t*XSTRIDE

    float c = 0.0f;

    // Prefetch time-block 0 into registers
    float xv[TBLK];
    #pragma unroll
    for (int tt = 0; tt < TBLK; tt++)
        xv[tt] = x[tt * XSTRIDE + xbase];

    for (int t0 = 0; t0 < L_SEQ; t0 += TBLK) {
        __syncthreads();                       // xs buffer free for reuse
        #pragma unroll
        for (int tt = 0; tt < TBLK; tt++)
            xs[tid * TBLK + tt] = xv[tt];
        __syncthreads();                       // xs (and W on first iter) visible

        // Keep this block's own-channel x for the highway term
        float xcur[TBLK];
        #pragma unroll
        for (int tt = 0; tt < TBLK; tt++) xcur[tt] = xv[tt];

        // Prefetch next block (latency hidden under the dot phase below)
        if (t0 + TBLK < L_SEQ) {
            #pragma unroll
            for (int tt = 0; tt < TBLK; tt++)
                xv[tt] = x[(t0 + TBLK + tt) * XSTRIDE + xbase];
        }

        // ---- Dot phase: 3 gates x 8 timesteps, packed as f32x2 time-pairs
        u64 aX[4], aF[4], aR[4];
        #pragma unroll
        for (int p = 0; p < 4; p++) { aX[p] = 0ull; aF[p] = 0ull; aR[p] = 0ull; }

        const u64* xs2 = (const u64*)xs;       // [k][4 pairs]
        #pragma unroll 16
        for (int k = 0; k < DIM; k++) {
            u64 x0 = xs2[k * 4 + 0];
            u64 x1 = xs2[k * 4 + 1];
            u64 x2 = xs2[k * 4 + 2];
            u64 x3 = xs2[k * 4 + 3];
            float wxs = Wx[k * 128 + tid];
            float wfs = Wf[k * 128 + tid];
            float wrs = Wr[k * 128 + tid];
            u64 wx2 = pack2(wxs, wxs);
            u64 wf2 = pack2(wfs, wfs);
            u64 wr2 = pack2(wrs, wrs);
            fma2(aX[0], wx2, x0); fma2(aX[1], wx2, x1);
            fma2(aX[2], wx2, x2); fma2(aX[3], wx2, x3);
            fma2(aF[0], wf2, x0); fma2(aF[1], wf2, x1);
            fma2(aF[2], wf2, x2); fma2(aF[3], wf2, x3);
            fma2(aR[0], wr2, x0); fma2(aR[1], wr2, x1);
            fma2(aR[2], wr2, x2); fma2(aR[3], wr2, x3);
        }

        // ---- Epilogue: gates first (independent, pipelines MUFU), then the scan
        float xt[TBLK], fpre[TBLK], rpre[TBLK];
        #pragma unroll
        for (int p = 0; p < 4; p++) {
            unpack2(aX[p], xt[2 * p],   xt[2 * p + 1]);
            unpack2(aF[p], fpre[2 * p], fpre[2 * p + 1]);
            unpack2(aR[p], rpre[2 * p], rpre[2 * p + 1]);
        }
        float fv[TBLK], rv[TBLK];
        #pragma unroll
        for (int t = 0; t < TBLK; t++) {
            fv[t] = sigmoidf_fast(fpre[t] + bfv);
            rv[t] = sigmoidf_fast(rpre[t] + brv);
        }
        #pragma unroll
        for (int t = 0; t < TBLK; t++) {
            c = fmaf(fv[t], c - xt[t], xt[t]);            // f*c + (1-f)*xt
            float h = fmaf(rv[t], c - xcur[t], xcur[t]);  // r*c + (1-r)*x
            outp[(t0 + t) * XSTRIDE] = h;
        }
    }
}

extern "C" void kernel_launch(void* const* d_in, const int* in_sizes, int n_in,
                              void* d_out, int out_size) {
    const float* x  = (const float*)d_in[0];
    const float* W  = (const float*)d_in[1];
    const float* bi = (const float*)d_in[2];
    float* out = (float*)d_out;

    cudaFuncSetAttribute(batch_sru_kernel,
                         cudaFuncAttributeMaxDynamicSharedMemorySize, SMEM_BYTES);
    batch_sru_kernel<<<BATCH * NBI, 128, SMEM_BYTES>>>(x, W, bi, out);
}

// round 2
// speedup vs baseline: 1.0674x; 1.0674x over previous
#include <cuda_runtime.h>

// BatchSRU: L=2048, B=8, D=128, NB=16  (fp32)
// One persistent CTA per (b,nb). W[nb] resident in SMEM. 256 threads:
//   j = tid & 127  -> output channel (and load lane k=j for x staging)
//   s = tid >> 7   -> time-slice: slice s computes timesteps [s*8, s*8+8) of a
//                     16-step time block. Dot phase fully parallel; the 16-step
//                     scan is serialized slice0 -> slice1 via a 1-float SMEM handoff.
// Inner dot loop per k: 12x fma.rn.f32x2 (time-pairs), 2x LDS.128 (x pairs),
// 1x LDS.64 (Wx/Wf interleaved), 1x LDS.32 (Wr).

#define L_SEQ 2048
#define BATCH 8
#define DIM   128
#define NBI   16
#define TBLK  16
#define XSTRIDE (BATCH * DIM * NBI)   // 16384 floats per timestep

typedef unsigned long long u64;

__device__ __forceinline__ u64 pack2(float lo, float hi) {
    u64 r; asm("mov.b64 %0, {%1, %2};" : "=l"(r) : "f"(lo), "f"(hi)); return r;
}
__device__ __forceinline__ void unpack2(u64 v, float& lo, float& hi) {
    asm("mov.b64 {%0, %1}, %2;" : "=f"(lo), "=f"(hi) : "l"(v));
}
__device__ __forceinline__ void fma2(u64& d, u64 a, u64 b) {
    asm("fma.rn.f32x2 %0, %1, %2, %0;" : "+l"(d) : "l"(a), "l"(b));
}
__device__ __forceinline__ float sigmoidf_fast(float z) {
    return __fdividef(1.0f, 1.0f + __expf(-z));
}

// SMEM layout (float offsets):
//   Wxf : float2[128k][128j]  -> 32768 floats (131072 B)
//   Wr  : float [128k][128j]  -> 16384 floats
//   xs  : ulonglong2[4 qgroups][128 k] (= 16 floats per k) -> 2048 floats
//   cprev[128], cmid[128]
#define OFF_WXF 0
#define OFF_WR  32768
#define OFF_XS  49152
#define OFF_CP  51200
#define OFF_CM  51328
#define SMEM_BYTES ((51456) * 4)      // 205824 B

__global__ void __launch_bounds__(256, 1) batch_sru_kernel(
    const float* __restrict__ x,
    const float* __restrict__ W,
    const float* __restrict__ bias,
    float* __restrict__ out)
{
    extern __shared__ float smem[];
    const int tid = threadIdx.x;
    const int j   = tid & 127;        // channel
    const int s   = tid >> 7;         // time slice (0 or 1)
    const int b   = blockIdx.x >> 4;
    const int nb  = blockIdx.x & 15;

    float2* Wxf = (float2*)(smem + OFF_WXF);
    float*  Wr  = smem + OFF_WR;
    ulonglong2* xs2 = (ulonglong2*)(smem + OFF_XS);
    float* cprev = smem + OFF_CP;
    float* cmid  = smem + OFF_CM;

    // ---- One-time: load W[nb] (128 x 384 row-major) into Wxf/Wr
    {
        const float4* Wg4 = (const float4*)(W + (size_t)nb * (DIM * 3 * DIM));
        #pragma unroll 4
        for (int idx = tid; idx < (DIM * 3 * DIM) / 4; idx += 256) {
            float4 v = Wg4[idx];
            int e  = idx * 4;
            int k  = e / 384;
            int h  = e - k * 384;
            int g  = h >> 7;
            int jj = h & 127;
            float vv[4] = {v.x, v.y, v.z, v.w};
            #pragma unroll
            for (int i = 0; i < 4; i++) {
                if (g == 0)      Wxf[k * 128 + jj + i].x = vv[i];
                else if (g == 1) Wxf[k * 128 + jj + i].y = vv[i];
                else             Wr [k * 128 + jj + i]   = vv[i];
            }
        }
    }
    if (tid < 128) cprev[tid] = 0.0f;

    const float bfv = bias[nb * 256 + j];
    const float brv = bias[nb * 256 + 128 + j];

    // x element for (t, b, k=j, nb)
    const int xbase = (b * DIM + j) * NBI + nb;
    float* outp = out + xbase;                 // + t*XSTRIDE

    // Prefetch this thread's 8 timesteps of block 0 (t = s*8 + tt)
    float xv[8];
    #pragma unroll
    for (int tt = 0; tt < 8; tt++)
        xv[tt] = x[(s * 8 + tt) * XSTRIDE + xbase];

    const int q0 = (s * 2) * 128;              // ulonglong2 group indices
    const int q1 = (s * 2 + 1) * 128;

    for (int t0 = 0; t0 < L_SEQ; t0 += TBLK) {
        // ---- Stage current block's x into SMEM (pairs packed as u64)
        {
            ulonglong2 pa, pb;
            pa.x = pack2(xv[0], xv[1]); pa.y = pack2(xv[2], xv[3]);
            pb.x = pack2(xv[4], xv[5]); pb.y = pack2(xv[6], xv[7]);
            xs2[q0 + j] = pa;
            xs2[q1 + j] = pb;
        }
        __syncthreads();                       // (b) xs + W + cprev visible

        float xcur[8];
        #pragma unroll
        for (int tt = 0; tt < 8; tt++) xcur[tt] = xv[tt];

        // Prefetch next block (hidden under the dot phase)
        if (t0 + TBLK < L_SEQ) {
            #pragma unroll
            for (int tt = 0; tt < 8; tt++)
                xv[tt] = x[(t0 + TBLK + s * 8 + tt) * XSTRIDE + xbase];
        }

        // ---- Dot phase: 3 gates x 8 timesteps (4 time-pairs), f32x2 FMAs
        u64 aX[4], aF[4], aR[4];
        #pragma unroll
        for (int p = 0; p < 4; p++) { aX[p] = 0ull; aF[p] = 0ull; aR[p] = 0ull; }

        #pragma unroll 8
        for (int k = 0; k < DIM; k++) {
            ulonglong2 xa = xs2[q0 + k];       // pairs 0,1 of this slice
            ulonglong2 xb = xs2[q1 + k];       // pairs 2,3
            float2 wxf = Wxf[k * 128 + j];
            float  wr  = Wr [k * 128 + j];
            u64 wx2 = pack2(wxf.x, wxf.x);
            u64 wf2 = pack2(wxf.y, wxf.y);
            u64 wr2 = pack2(wr,    wr);
            fma2(aX[0], wx2, xa.x); fma2(aX[1], wx2, xa.y);
            fma2(aX[2], wx2, xb.x); fma2(aX[3], wx2, xb.y);
            fma2(aF[0], wf2, xa.x); fma2(aF[1], wf2, xa.y);
            fma2(aF[2], wf2, xb.x); fma2(aF[3], wf2, xb.y);
            fma2(aR[0], wr2, xa.x); fma2(aR[1], wr2, xa.y);
            fma2(aR[2], wr2, xb.x); fma2(aR[3], wr2, xb.y);
        }

        // ---- Gates (both slices in parallel; pipelines the MUFU work)
        float xt[8], fp[8], rp[8];
        #pragma unroll
        for (int p = 0; p < 4; p++) {
            unpack2(aX[p], xt[2*p], xt[2*p+1]);
            unpack2(aF[p], fp[2*p], fp[2*p+1]);
            unpack2(aR[p], rp[2*p], rp[2*p+1]);
        }
        float fv[8], rv[8];
        #pragma unroll
        for (int t = 0; t < 8; t++) {
            fv[t] = sigmoidf_fast(fp[t] + bfv);
            rv[t] = sigmoidf_fast(rp[t] + brv);
        }

        // ---- Scan: slice 0 does t0..t0+7, hands c to slice 1 for t0+8..t0+15
        if (s == 0) {
            float c = cprev[j];
            #pragma unroll
            for (int t = 0; t < 8; t++) {
                c = fmaf(fv[t], c - xt[t], xt[t]);             // f*c + (1-f)*xt
                float h = fmaf(rv[t], c - xcur[t], xcur[t]);   // r*c + (1-r)*x
                outp[(t0 + t) * XSTRIDE] = h;
            }
            cmid[j] = c;
        }
        __syncthreads();                       // (c) cmid ready
        if (s == 1) {
            float c = cmid[j];
            #pragma unroll
            for (int t = 0; t < 8; t++) {
                c = fmaf(fv[t], c - xt[t], xt[t]);
                float h = fmaf(rv[t], c - xcur[t], xcur[t]);
                outp[(t0 + 8 + t) * XSTRIDE] = h;
            }
            cprev[j] = c;                      // consumed after next barrier
        }
        // next iteration's xs store is safe: all xs reads completed before (c)
    }
}

extern "C" void kernel_launch(void* const* d_in, const int* in_sizes, int n_in,
                              void* d_out, int out_size) {
    const float* x  = (const float*)d_in[0];
    const float* W  = (const float*)d_in[1];
    const float* bi = (const float*)d_in[2];
    float* out = (float*)d_out;

    cudaFuncSetAttribute(batch_sru_kernel,
                         cudaFuncAttributeMaxDynamicSharedMemorySize, SMEM_BYTES);
    batch_sru_kernel<<<BATCH * NBI, 256, SMEM_BYTES>>>(x, W, bi, out);
}